// round 12
// baseline (speedup 1.0000x reference)
#include <cuda_runtime.h>
#include <cuda_bf16.h>

// ManagerStateTracker: B=1024, P=64, N=512, E=256, F=64
// out row (width 12800):
//   [0,64) feas  [64,192) work  [192,4288) known  [4288,8384) unknown
//   [8384,12480) differ  [12480,12544) qa
//   [12544,12800) agg_state = mean_p tanh(embed[b, nodes[b,p], :] @ W + b)

#define BDIM 1024
#define PDIM 64
#define NDIM 512
#define EDIM 256
#define OUTW 12800
#define COPYW 12544

#define XPAD 264   // X smem pitch (bf16): 528B = 33*16B -> conflict-free ldmatrix

// W pre-packed into mma B-fragment order:
// g_Wfrag[w(8)][kstep(16)][nt(4)][lane(32)] = uint2{b0, b1}
__device__ uint2 g_Wfrag[8 * 16 * 4 * 32];   // 128KB, L2/L1-hot

__device__ __forceinline__ float tanh_fast(float x) {
    asm("tanh.approx.f32 %0, %0;" : "+f"(x)); return x;
}

__device__ __forceinline__ void mma_bf16(float& d0, float& d1, float& d2, float& d3,
                                         unsigned a0, unsigned a1, unsigned a2, unsigned a3,
                                         unsigned b0, unsigned b1) {
    asm("mma.sync.aligned.m16n8k16.row.col.f32.bf16.bf16.f32 "
        "{%0,%1,%2,%3}, {%4,%5,%6,%7}, {%8,%9}, {%0,%1,%2,%3};"
        : "+f"(d0), "+f"(d1), "+f"(d2), "+f"(d3)
        : "r"(a0), "r"(a1), "r"(a2), "r"(a3), "r"(b0), "r"(b1));
}

__device__ __forceinline__ void ldsm_x4(unsigned& r0, unsigned& r1,
                                        unsigned& r2, unsigned& r3, const void* p) {
    unsigned addr = (unsigned)__cvta_generic_to_shared(p);
    asm volatile("ldmatrix.sync.aligned.m8n8.x4.shared.b16 {%0,%1,%2,%3}, [%4];"
                 : "=r"(r0), "=r"(r1), "=r"(r2), "=r"(r3) : "r"(addr));
}

// ---------------------------------------------------------------------------
// Kernel 0: W (E,E) fp32 [k][n] -> fragment-packed bf16 g_Wfrag
// ---------------------------------------------------------------------------
__global__ void wconv_kernel(const float* __restrict__ W) {
    int idx = blockIdx.x * blockDim.x + threadIdx.x;   // 16384 slots
    int lane = idx & 31;
    int nt   = (idx >> 5) & 3;
    int ks   = (idx >> 7) & 15;
    int w    = idx >> 11;
    int g  = lane >> 2;
    int t4 = lane & 3;
    int n  = w * 32 + nt * 8 + g;
    int k0 = ks * 16 + 2 * t4;
    __nv_bfloat162 lo = __floats2bfloat162_rn(W[(k0)     * EDIM + n],
                                              W[(k0 + 1) * EDIM + n]);
    __nv_bfloat162 hi = __floats2bfloat162_rn(W[(k0 + 8) * EDIM + n],
                                              W[(k0 + 9) * EDIM + n]);
    g_Wfrag[idx] = make_uint2(*reinterpret_cast<unsigned*>(&lo),
                              *reinterpret_cast<unsigned*>(&hi));
}

// ---------------------------------------------------------------------------
// Kernel 1: fused gather + concat copy + HMMA GEMM + tanh/mean.
// One CTA per batch, 512 threads (16 warps).
// Warp w: m-half (w>>3)*32, n-slice (w&7)*32  -> acc 32 fp32/thread.
// smem: Xs[64][XPAD] bf16 (33KB) + partial[2][256] f32 (2KB) = 35.8KB.
// __launch_bounds__(512,2) -> 64 regs -> 32 warps/SM.
// ---------------------------------------------------------------------------
__global__ void __launch_bounds__(512, 2)
fused_kernel(const float* __restrict__ feas,
             const float* __restrict__ work,
             const float* __restrict__ known,
             const float* __restrict__ unknown,
             const float* __restrict__ differ,
             const float* __restrict__ qa,
             const int*   __restrict__ nodes32,   // int32 OR int64 (probed)
             const float* __restrict__ embed,     // (B, N, E)
             const float* __restrict__ bias,      // (E,)
             float* __restrict__ out) {
    extern __shared__ char smraw[];
    __nv_bfloat16* Xs = reinterpret_cast<__nv_bfloat16*>(smraw);        // [64][XPAD]
    float* Pp = reinterpret_cast<float*>(smraw + PDIM * XPAD * 2);      // [2][256]

    const int b    = blockIdx.x;
    const int t    = threadIdx.x;
    const int lane = t & 31;
    const int warp = t >> 5;          // 0..15
    const int mh   = warp >> 3;       // m-half 0/1
    const int nw   = warp & 7;        // n-warp 0..7

    // ---- int64 probe, per-warp, barrier-free.
    // If dtype is int64 (values < 512) all 32 high words are 0.
    // P(false positive for random int32 in [0,512)) = (1/512)^32 ~ 0.
    const bool is64 =
        (__ballot_sync(0xffffffffu, nodes32[2 * lane + 1] != 0) == 0u);

    // ---- Phase 1: gather X rows 4w..4w+3 (row-contiguous LDG.128, nL=4).
    {
        const int gi0 = b * PDIM + warp * 4;
        int myn = 0;
        if (lane < 4)
            myn = is64 ? nodes32[2 * (gi0 + lane)] : nodes32[gi0 + lane];
        #pragma unroll
        for (int r = 0; r < 4; r++) {
            const int node = __shfl_sync(0xffffffffu, myn, r);
            const float4* src =
                reinterpret_cast<const float4*>(embed + ((size_t)b * NDIM + node) * EDIM);
            float4 v0 = src[lane];
            float4 v1 = src[lane + 32];
            __nv_bfloat162 a0 = __floats2bfloat162_rn(v0.x, v0.y);
            __nv_bfloat162 a1 = __floats2bfloat162_rn(v0.z, v0.w);
            __nv_bfloat162 c0 = __floats2bfloat162_rn(v1.x, v1.y);
            __nv_bfloat162 c1 = __floats2bfloat162_rn(v1.z, v1.w);
            __nv_bfloat16* drow = Xs + (warp * 4 + r) * XPAD;
            reinterpret_cast<uint2*>(drow + lane * 4)[0] =
                make_uint2(*reinterpret_cast<unsigned*>(&a0),
                           *reinterpret_cast<unsigned*>(&a1));
            reinterpret_cast<uint2*>(drow + 128 + lane * 4)[0] =
                make_uint2(*reinterpret_cast<unsigned*>(&c0),
                           *reinterpret_cast<unsigned*>(&c1));
        }
    }

    // ---- Phase 2: concat copy (independent; fills gather-latency window).
    {
        float* orow = out + (size_t)b * OUTW;
        const float* bsrc[3] = { known   + b * 4096,
                                 unknown + b * 4096,
                                 differ  + b * 4096 };
        float4 v[6];
        #pragma unroll
        for (int j = 0; j < 6; j++) {
            int idx = t + j * 512;              // 0..3071
            v[j] = reinterpret_cast<const float4*>(bsrc[idx >> 10])[idx & 1023];
        }
        #pragma unroll
        for (int j = 0; j < 6; j++) {
            int idx = t + j * 512;
            reinterpret_cast<float4*>(orow + 192 + (idx >> 10) * 4096)[idx & 1023] = v[j];
        }
        if (t < 64) {
            const float* src;
            int c;
            if (t < 16)      { src = feas + b * 64  + 4 * t;        c = 4 * t; }
            else if (t < 48) { src = work + b * 128 + 4 * (t - 16); c = 64 + 4 * (t - 16); }
            else             { src = qa   + b * 64  + 4 * (t - 48); c = 12480 + 4 * (t - 48); }
            *reinterpret_cast<float4*>(orow + c) =
                *reinterpret_cast<const float4*>(src);
        }
    }
    __syncthreads();   // Xs ready

    // ---- Phase 3: GEMM. Warp tile: 32(m) x 32(n). B-frags coalesced LDG.64.
    const int g    = lane >> 2;
    const int t4   = lane & 3;
    const int nb   = nw * 32;
    const int lrow = lane & 15;
    const int lcol = (lane >> 4) * 8;

    float acc[2][4][4];
    #pragma unroll
    for (int mt = 0; mt < 2; mt++)
        #pragma unroll
        for (int nt = 0; nt < 4; nt++)
            #pragma unroll
            for (int j = 0; j < 4; j++) acc[mt][nt][j] = 0.0f;

    const uint2* wf_base = g_Wfrag + nw * (16 * 4 * 32) + lane;

    #pragma unroll
    for (int ks = 0; ks < 16; ks++) {
        const int k0 = ks * 16;
        uint2 bf[4];
        #pragma unroll
        for (int nt = 0; nt < 4; nt++)
            bf[nt] = __ldg(wf_base + (ks * 4 + nt) * 32);
        #pragma unroll
        for (int mt = 0; mt < 2; mt++) {
            unsigned a0, a1, a2, a3;
            ldsm_x4(a0, a1, a2, a3,
                    Xs + (mh * 32 + mt * 16 + lrow) * XPAD + k0 + lcol);
            #pragma unroll
            for (int nt = 0; nt < 4; nt++)
                mma_bf16(acc[mt][nt][0], acc[mt][nt][1],
                         acc[mt][nt][2], acc[mt][nt][3],
                         a0, a1, a2, a3, bf[nt].x, bf[nt].y);
        }
    }

    // ---- Epilogue: tanh(.+bias), sum over this warp's 32 rows, shfl over g.
    float s0[4], s1[4];
    #pragma unroll
    for (int nt = 0; nt < 4; nt++) {
        const int c = nb + nt * 8 + 2 * t4;
        const float bz0 = __ldg(bias + c);
        const float bz1 = __ldg(bias + c + 1);
        float a = 0.f, bsum = 0.f;
        #pragma unroll
        for (int mt = 0; mt < 2; mt++) {
            a    += tanh_fast(acc[mt][nt][0] + bz0) + tanh_fast(acc[mt][nt][2] + bz0);
            bsum += tanh_fast(acc[mt][nt][1] + bz1) + tanh_fast(acc[mt][nt][3] + bz1);
        }
        s0[nt] = a; s1[nt] = bsum;
    }
    #pragma unroll
    for (int off = 4; off <= 16; off <<= 1) {
        #pragma unroll
        for (int nt = 0; nt < 4; nt++) {
            s0[nt] += __shfl_xor_sync(0xffffffffu, s0[nt], off);
            s1[nt] += __shfl_xor_sync(0xffffffffu, s1[nt], off);
        }
    }
    if (g == 0) {                    // lanes 0..3 hold 32-row column sums
        #pragma unroll
        for (int nt = 0; nt < 4; nt++) {
            const int c = nb + nt * 8 + 2 * t4;
            Pp[mh * 256 + c]     = s0[nt];
            Pp[mh * 256 + c + 1] = s1[nt];
        }
    }
    __syncthreads();   // partials ready

    if (t < 256)
        out[(size_t)b * OUTW + COPYW + t] =
            (Pp[t] + Pp[256 + t]) * (1.0f / (float)PDIM);
}

// ---------------------------------------------------------------------------
extern "C" void kernel_launch(void* const* d_in, const int* in_sizes, int n_in,
                              void* d_out, int out_size) {
    const float* feas    = (const float*)d_in[0];
    const float* work    = (const float*)d_in[1];
    const float* known   = (const float*)d_in[2];
    const float* unknown = (const float*)d_in[3];
    const float* differ  = (const float*)d_in[4];
    const float* qa      = (const float*)d_in[5];
    const int*   nodes   = (const int*)d_in[6];
    const float* embed   = (const float*)d_in[7];
    const float* W       = (const float*)d_in[8];
    const float* bias    = (const float*)d_in[9];
    float* out = (float*)d_out;

    const int smem_bytes = PDIM * XPAD * sizeof(__nv_bfloat16)     // 33792
                         + 2 * EDIM * sizeof(float);               // + 2048

    wconv_kernel<<<64, 256>>>(W);
    fused_kernel<<<BDIM, 512, smem_bytes>>>(
        feas, work, known, unknown, differ, qa, nodes, embed, bias, out);
}

// round 13
// speedup vs baseline: 1.0992x; 1.0992x over previous
#include <cuda_runtime.h>
#include <cuda_bf16.h>

// ManagerStateTracker: B=1024, P=64, N=512, E=256, F=64
// out row (width 12800):
//   [0,64) feas  [64,192) work  [192,4288) known  [4288,8384) unknown
//   [8384,12480) differ  [12480,12544) qa
//   [12544,12800) agg_state = mean_p tanh(embed[b, nodes[b,p], :] @ W + b)

#define BDIM 1024
#define PDIM 64
#define NDIM 512
#define EDIM 256
#define OUTW 12800
#define COPYW 12544

#define XPAD 264   // X smem pitch (bf16): 528B = 33*16B -> conflict-free ldmatrix

// W pre-packed into mma B-fragment order:
// g_Wfrag[w(8)][kstep(16)][nt(4)][lane(32)] = uint2{b0, b1}
__device__ uint2 g_Wfrag[8 * 16 * 4 * 32];   // 128KB, L1-resident per SM

__device__ __forceinline__ float tanh_fast(float x) {
    asm("tanh.approx.f32 %0, %0;" : "+f"(x)); return x;
}

__device__ __forceinline__ void mma_bf16(float& d0, float& d1, float& d2, float& d3,
                                         unsigned a0, unsigned a1, unsigned a2, unsigned a3,
                                         unsigned b0, unsigned b1) {
    asm("mma.sync.aligned.m16n8k16.row.col.f32.bf16.bf16.f32 "
        "{%0,%1,%2,%3}, {%4,%5,%6,%7}, {%8,%9}, {%0,%1,%2,%3};"
        : "+f"(d0), "+f"(d1), "+f"(d2), "+f"(d3)
        : "r"(a0), "r"(a1), "r"(a2), "r"(a3), "r"(b0), "r"(b1));
}

__device__ __forceinline__ void ldsm_x4(unsigned& r0, unsigned& r1,
                                        unsigned& r2, unsigned& r3, const void* p) {
    unsigned addr = (unsigned)__cvta_generic_to_shared(p);
    asm volatile("ldmatrix.sync.aligned.m8n8.x4.shared.b16 {%0,%1,%2,%3}, [%4];"
                 : "=r"(r0), "=r"(r1), "=r"(r2), "=r"(r3) : "r"(addr));
}

// ---------------------------------------------------------------------------
// Kernel 0: W (E,E) fp32 [k][n] -> fragment-packed bf16 g_Wfrag
// ---------------------------------------------------------------------------
__global__ void wconv_kernel(const float* __restrict__ W) {
    int idx = blockIdx.x * blockDim.x + threadIdx.x;   // 16384 slots
    int lane = idx & 31;
    int nt   = (idx >> 5) & 3;
    int ks   = (idx >> 7) & 15;
    int w    = idx >> 11;
    int g  = lane >> 2;
    int t4 = lane & 3;
    int n  = w * 32 + nt * 8 + g;
    int k0 = ks * 16 + 2 * t4;
    __nv_bfloat162 lo = __floats2bfloat162_rn(W[(k0)     * EDIM + n],
                                              W[(k0 + 1) * EDIM + n]);
    __nv_bfloat162 hi = __floats2bfloat162_rn(W[(k0 + 8) * EDIM + n],
                                              W[(k0 + 9) * EDIM + n]);
    g_Wfrag[idx] = make_uint2(*reinterpret_cast<unsigned*>(&lo),
                              *reinterpret_cast<unsigned*>(&hi));
}

// ---------------------------------------------------------------------------
// Kernel 1: fused gather + HMMA GEMM with copy INTERLEAVED into the ks loop.
// One CTA per batch, 256 threads (8 warps). Warp w: n-slice [32w, 32w+32).
// smem: Xs[64][XPAD] bf16 = 33KB. 2 CTAs/SM.
// Copy schedule (12 float4/thread):
//   j=0..5  : load+store before the barrier (fills gather-latency window)
//   j=6..11 : load at ks=(j-6)*2, store at ks=(j-6)*2+5  (inside MMA loop)
// ---------------------------------------------------------------------------
__global__ void __launch_bounds__(256, 2)
fused_kernel(const float* __restrict__ feas,
             const float* __restrict__ work,
             const float* __restrict__ known,
             const float* __restrict__ unknown,
             const float* __restrict__ differ,
             const float* __restrict__ qa,
             const int*   __restrict__ nodes32,   // int32 OR int64 (probed)
             const float* __restrict__ embed,     // (B, N, E)
             const float* __restrict__ bias,      // (E,)
             float* __restrict__ out) {
    extern __shared__ char smraw[];
    __nv_bfloat16* Xs = reinterpret_cast<__nv_bfloat16*>(smraw);  // [64][XPAD]

    const int b    = blockIdx.x;
    const int t    = threadIdx.x;
    const int lane = t & 31;
    const int warp = t >> 5;

    // ---- int64 probe, per-warp, barrier-free.
    // If dtype is int64 (values < 512) all 32 high words are 0.
    // P(false positive for random int32 in [0,512)) = (1/512)^32 ~ 0.
    const bool is64 =
        (__ballot_sync(0xffffffffu, nodes32[2 * lane + 1] != 0) == 0u);

    float* orow = out + (size_t)b * OUTW;
    const float* bsrc[3] = { known   + b * 4096,
                             unknown + b * 4096,
                             differ  + b * 4096 };

    // ---- Phase 1: gather X rows 8w..8w+7, row-contiguous (nL=4 per LDG.128).
    {
        const int gi0 = b * PDIM + warp * 8;
        int myn = 0;
        if (lane < 8)
            myn = is64 ? nodes32[2 * (gi0 + lane)] : nodes32[gi0 + lane];
        #pragma unroll
        for (int r = 0; r < 8; r++) {
            const int node = __shfl_sync(0xffffffffu, myn, r);
            const float4* src =
                reinterpret_cast<const float4*>(embed + ((size_t)b * NDIM + node) * EDIM);
            float4 v0 = src[lane];
            float4 v1 = src[lane + 32];
            __nv_bfloat162 a0 = __floats2bfloat162_rn(v0.x, v0.y);
            __nv_bfloat162 a1 = __floats2bfloat162_rn(v0.z, v0.w);
            __nv_bfloat162 c0 = __floats2bfloat162_rn(v1.x, v1.y);
            __nv_bfloat162 c1 = __floats2bfloat162_rn(v1.z, v1.w);
            __nv_bfloat16* drow = Xs + (warp * 8 + r) * XPAD;
            reinterpret_cast<uint2*>(drow + lane * 4)[0] =
                make_uint2(*reinterpret_cast<unsigned*>(&a0),
                           *reinterpret_cast<unsigned*>(&a1));
            reinterpret_cast<uint2*>(drow + 128 + lane * 4)[0] =
                make_uint2(*reinterpret_cast<unsigned*>(&c0),
                           *reinterpret_cast<unsigned*>(&c1));
        }
    }

    // ---- Phase 2: first half of the copy (fills gather-latency window).
    {
        float4 v[6];
        #pragma unroll
        for (int j = 0; j < 6; j++) {
            int idx = t + j * 256;
            v[j] = reinterpret_cast<const float4*>(bsrc[idx >> 10])[idx & 1023];
        }
        #pragma unroll
        for (int j = 0; j < 6; j++) {
            int idx = t + j * 256;
            reinterpret_cast<float4*>(orow + 192 + (idx >> 10) * 4096)[idx & 1023] = v[j];
        }
    }
    __syncthreads();   // Xs ready

    // ---- Phase 3: GEMM with second copy-half interleaved.
    const int g    = lane >> 2;
    const int t4   = lane & 3;
    const int nb   = warp * 32;
    const int lrow = lane & 15;
    const int lcol = (lane >> 4) * 8;

    float acc[4][4][4];
    #pragma unroll
    for (int mt = 0; mt < 4; mt++)
        #pragma unroll
        for (int nt = 0; nt < 4; nt++)
            #pragma unroll
            for (int j = 0; j < 4; j++) acc[mt][nt][j] = 0.0f;

    const uint2* wf_base = g_Wfrag + warp * (16 * 4 * 32) + lane;
    float4 cl[3];      // rotating copy-load buffer (max 3 in flight)

    #pragma unroll
    for (int ks = 0; ks < 16; ks++) {
        const int k0 = ks * 16;
        uint2 bf[4];
        #pragma unroll
        for (int nt = 0; nt < 4; nt++)
            bf[nt] = __ldg(wf_base + (ks * 4 + nt) * 32);

        // interleaved copy load: j = 6 + ks/2 at even ks
        if ((ks & 1) == 0 && ks <= 10) {
            int j = 6 + (ks >> 1);
            int idx = t + j * 256;
            cl[(ks >> 1) % 3] =
                reinterpret_cast<const float4*>(bsrc[idx >> 10])[idx & 1023];
        }

        #pragma unroll
        for (int mt = 0; mt < 4; mt++) {
            unsigned a0, a1, a2, a3;
            ldsm_x4(a0, a1, a2, a3, Xs + (mt * 16 + lrow) * XPAD + k0 + lcol);
            #pragma unroll
            for (int nt = 0; nt < 4; nt++)
                mma_bf16(acc[mt][nt][0], acc[mt][nt][1],
                         acc[mt][nt][2], acc[mt][nt][3],
                         a0, a1, a2, a3, bf[nt].x, bf[nt].y);
        }

        // interleaved copy store: j = 6 + (ks-5)/2 at odd ks >= 5
        if ((ks & 1) == 1 && ks >= 5) {
            int j = 6 + ((ks - 5) >> 1);
            int idx = t + j * 256;
            reinterpret_cast<float4*>(orow + 192 + (idx >> 10) * 4096)[idx & 1023] =
                cl[((ks - 5) >> 1) % 3];
        }
    }

    // ---- Epilogue: tanh(.+bias), sum over M, shfl-reduce over g.
    float s0[4], s1[4];
    #pragma unroll
    for (int nt = 0; nt < 4; nt++) {
        const int c = nb + nt * 8 + 2 * t4;
        const float bz0 = __ldg(bias + c);
        const float bz1 = __ldg(bias + c + 1);
        float a = 0.f, bsum = 0.f;
        #pragma unroll
        for (int mt = 0; mt < 4; mt++) {
            a    += tanh_fast(acc[mt][nt][0] + bz0) + tanh_fast(acc[mt][nt][2] + bz0);
            bsum += tanh_fast(acc[mt][nt][1] + bz1) + tanh_fast(acc[mt][nt][3] + bz1);
        }
        s0[nt] = a; s1[nt] = bsum;
    }
    #pragma unroll
    for (int off = 4; off <= 16; off <<= 1) {
        #pragma unroll
        for (int nt = 0; nt < 4; nt++) {
            s0[nt] += __shfl_xor_sync(0xffffffffu, s0[nt], off);
            s1[nt] += __shfl_xor_sync(0xffffffffu, s1[nt], off);
        }
    }
    if (g == 0) {
        float* arow = orow + COPYW;
        #pragma unroll
        for (int nt = 0; nt < 4; nt++) {
            const int c = nb + nt * 8 + 2 * t4;
            arow[c]     = s0[nt] * (1.0f / (float)PDIM);
            arow[c + 1] = s1[nt] * (1.0f / (float)PDIM);
        }
    }

    // ---- Small copy blocks (trailing, tiny).
    if (t < 64) {
        const float* src;
        int c;
        if (t < 16)      { src = feas + b * 64  + 4 * t;        c = 4 * t; }
        else if (t < 48) { src = work + b * 128 + 4 * (t - 16); c = 64 + 4 * (t - 16); }
        else             { src = qa   + b * 64  + 4 * (t - 48); c = 12480 + 4 * (t - 48); }
        *reinterpret_cast<float4*>(orow + c) =
            *reinterpret_cast<const float4*>(src);
    }
}

// ---------------------------------------------------------------------------
extern "C" void kernel_launch(void* const* d_in, const int* in_sizes, int n_in,
                              void* d_out, int out_size) {
    const float* feas    = (const float*)d_in[0];
    const float* work    = (const float*)d_in[1];
    const float* known   = (const float*)d_in[2];
    const float* unknown = (const float*)d_in[3];
    const float* differ  = (const float*)d_in[4];
    const float* qa      = (const float*)d_in[5];
    const int*   nodes   = (const int*)d_in[6];
    const float* embed   = (const float*)d_in[7];
    const float* W       = (const float*)d_in[8];
    const float* bias    = (const float*)d_in[9];
    float* out = (float*)d_out;

    const int smem_bytes = PDIM * XPAD * sizeof(__nv_bfloat16);   // 33792 < 48KB

    wconv_kernel<<<64, 256>>>(W);
    fused_kernel<<<BDIM, 256, smem_bytes>>>(
        feas, work, known, unknown, differ, qa, nodes, embed, bias, out);
}